// round 5
// baseline (speedup 1.0000x reference)
#include <cuda_runtime.h>

#define N_PATHS 1000000
#define N_LINKS 50000
#define K_HOPS  8
#define N_REP   8

#define PERS_CTAS    148
#define PERS_THREADS 1024
#define N_GROUPS     (N_PATHS / 4)
#define SMEM_BYTES   (N_LINKS * 4)   // 195.3 KB, under the 227 KB opt-in cap

// Scratch: __device__ globals. Zero-init at module load; link_update re-zeroes
// g_T each pass, so the invariant holds across graph replays.
__device__ float g_T[N_REP][N_LINKS];
__device__ float g_bp[N_LINKS];
__device__ float g_Xl[N_LINKS];

// Extract A = P[:,1] for 4 consecutive paths via 3 float4 loads.
// 3*p0 is a multiple of 12 -> 16B-aligned address.
__device__ __forceinline__ void load_A4(const float* __restrict__ P, int p0,
                                        float& t0, float& t1, float& t2, float& t3) {
    const float4* P4 = reinterpret_cast<const float4*>(P + 3 * p0);
    float4 a = __ldg(&P4[0]);
    float4 b = __ldg(&P4[1]);
    float4 c = __ldg(&P4[2]);
    t0 = a.y;   // 3p0+1
    t1 = b.x;   // 3p0+4
    t2 = b.w;   // 3p0+7
    t3 = c.z;   // 3p0+10
}

// Pass 1: bp == 0.5 everywhere -> t_k = A[p] * 0.5^k. No gathers.
__global__ void __launch_bounds__(128) traffic_pass1_kernel(const float* __restrict__ P,
                                                            const int*   __restrict__ edges) {
    int g = blockIdx.x * blockDim.x + threadIdx.x;
    if (g >= N_GROUPS) return;
    int p0 = g * 4;
    float* __restrict__ T = g_T[threadIdx.x & (N_REP - 1)];

    float t0, t1, t2, t3;
    load_A4(P, p0, t0, t1, t2, t3);

#pragma unroll
    for (int k = 0; k < K_HOPS; k++) {
        int4 e4 = *reinterpret_cast<const int4*>(edges + (size_t)k * N_PATHS + p0);
        atomicAdd(&T[e4.x - N_PATHS], t0);
        atomicAdd(&T[e4.y - N_PATHS], t1);
        atomicAdd(&T[e4.z - N_PATHS], t2);
        atomicAdd(&T[e4.w - N_PATHS], t3);
        t0 *= 0.5f; t1 *= 0.5f; t2 *= 0.5f; t3 *= 0.5f;
    }
}

// Passes 2/3: bp staged into shared memory (random gathers via LDS, ~8x
// cheaper than per-lane L1tex wavefronts). Atomics stay global REDG.
// One CTA per SM (smem-bound), grid-stride over path groups.
__global__ void __launch_bounds__(PERS_THREADS, 1)
traffic_smem_kernel(const float* __restrict__ P, const int* __restrict__ edges) {
    extern __shared__ float s_bp[];

    // Cooperative bp stage: 12500 float4, coalesced.
    const float4* bp4 = reinterpret_cast<const float4*>(g_bp);
    float4*       sb4 = reinterpret_cast<float4*>(s_bp);
    for (int i = threadIdx.x; i < N_LINKS / 4; i += PERS_THREADS)
        sb4[i] = bp4[i];
    __syncthreads();

    float* __restrict__ T = g_T[threadIdx.x & (N_REP - 1)];
    const int stride = gridDim.x * PERS_THREADS;

    for (int g = blockIdx.x * PERS_THREADS + threadIdx.x; g < N_GROUPS; g += stride) {
        int p0 = g * 4;
        float t0, t1, t2, t3;
        load_A4(P, p0, t0, t1, t2, t3);

#pragma unroll
        for (int k = 0; k < K_HOPS; k++) {
            int4 e4 = *reinterpret_cast<const int4*>(edges + (size_t)k * N_PATHS + p0);
            int e0 = e4.x - N_PATHS;
            int e1 = e4.y - N_PATHS;
            int e2 = e4.z - N_PATHS;
            int e3 = e4.w - N_PATHS;

            atomicAdd(&T[e0], t0);
            atomicAdd(&T[e1], t1);
            atomicAdd(&T[e2], t2);
            atomicAdd(&T[e3], t3);

            t0 *= 1.0f - s_bp[e0];
            t1 *= 1.0f - s_bp[e1];
            t2 *= 1.0f - s_bp[e2];
            t3 *= 1.0f - s_bp[e3];
        }
    }
}

// Mid-iteration link update, float4-vectorized: rho = (sum_r T_r)/cap,
// bp = (1-rho)rho^32/(1-rho^33+1e-8). Re-zeroes g_T.
__global__ void link_update_kernel(const float* __restrict__ L) {
    int i = blockIdx.x * blockDim.x + threadIdx.x;   // float4 index
    if (i >= N_LINKS / 4) return;

    float4 Tv = make_float4(0.f, 0.f, 0.f, 0.f);
#pragma unroll
    for (int r = 0; r < N_REP; r++) {
        float4* p = reinterpret_cast<float4*>(g_T[r]) + i;
        float4 v = *p;
        Tv.x += v.x; Tv.y += v.y; Tv.z += v.z; Tv.w += v.w;
        *p = make_float4(0.f, 0.f, 0.f, 0.f);
    }

    float4 Lv = __ldg(reinterpret_cast<const float4*>(L) + i);
    float4 bpv, rhov;
    float* tp = &Tv.x; float* lp = &Lv.x; float* bq = &bpv.x; float* rq = &rhov.x;
#pragma unroll
    for (int j = 0; j < 4; j++) {
        float rho = tp[j] / (lp[j] / 1000.0f);
        float r2 = rho * rho, r4 = r2 * r2, r8 = r4 * r4, r16 = r8 * r8, r32 = r16 * r16;
        bq[j] = (1.0f - rho) * r32 / (1.0f - r32 * rho + 1e-8f);
        rq[j] = rho;
    }
    reinterpret_cast<float4*>(g_bp)[i] = bpv;
    (void)rhov;
    // rho is recomputed in the final kernel; only bp must persist here.
}

// Final link update (iteration 3) fused with the per-link epilogue.
__global__ void link_update_final_kernel(const float* __restrict__ L,
                                         float* __restrict__ out) {
    int l = blockIdx.x * blockDim.x + threadIdx.x;
    if (l >= N_LINKS) return;

    float Tl = 0.0f;
#pragma unroll
    for (int r = 0; r < N_REP; r++) { Tl += g_T[r][l]; g_T[r][l] = 0.0f; }

    float Lraw = __ldg(&L[l]);
    float rho  = Tl / (Lraw / 1000.0f);

    float r2 = rho * rho, r4 = r2 * r2, r8 = r4 * r4, r16 = r8 * r8, r32 = r16 * r16;
    float r33 = r32 * rho;

    float pi0 = (1.0f - rho) / (1.0f - r33);

    float s = 1.0f, pw = 1.0f;
#pragma unroll
    for (int m = 1; m <= 32; m++) { pw *= rho; s += (float)m * pw; }

    float Lq   = pi0 * s / 32.0f;
    float pi0f = pi0 * r32;
    float Xl   = Lq * 32000.0f / Lraw;

    g_Xl[l] = Xl;

    out[N_PATHS + 3 * l + 0] = Lq;
    out[N_PATHS + 3 * l + 1] = rho;
    out[N_PATHS + 3 * l + 2] = pi0f;
}

// res[p] = sum_k X_l[e[k,p]] with X_l staged in smem.
__global__ void __launch_bounds__(PERS_THREADS, 1)
final_path_kernel(const int* __restrict__ edges, float* __restrict__ out) {
    extern __shared__ float s_xl[];

    const float4* xl4 = reinterpret_cast<const float4*>(g_Xl);
    float4*       sx4 = reinterpret_cast<float4*>(s_xl);
    for (int i = threadIdx.x; i < N_LINKS / 4; i += PERS_THREADS)
        sx4[i] = xl4[i];
    __syncthreads();

    const int stride = gridDim.x * PERS_THREADS;
    for (int g = blockIdx.x * PERS_THREADS + threadIdx.x; g < N_GROUPS; g += stride) {
        int p0 = g * 4;
        float s0 = 0.f, s1 = 0.f, s2 = 0.f, s3 = 0.f;
#pragma unroll
        for (int k = 0; k < K_HOPS; k++) {
            int4 e4 = *reinterpret_cast<const int4*>(edges + (size_t)k * N_PATHS + p0);
            s0 += s_xl[e4.x - N_PATHS];
            s1 += s_xl[e4.y - N_PATHS];
            s2 += s_xl[e4.z - N_PATHS];
            s3 += s_xl[e4.w - N_PATHS];
        }
        *reinterpret_cast<float4*>(out + p0) = make_float4(s0, s1, s2, s3);
    }
}

extern "C" void kernel_launch(void* const* d_in, const int* in_sizes, int n_in,
                              void* d_out, int out_size) {
    const float* P     = (const float*)d_in[0];   // (N_PATHS, 3)
    const float* L     = (const float*)d_in[1];   // (N_LINKS, 1)
    // d_in[2] = pl_paths: identity, unused
    const int*   edges = (const int*)d_in[3];     // (K_HOPS, N_PATHS)
    float* out = (float*)d_out;

    // Opt-in to >48KB dynamic smem (idempotent; not a stream-ordered op).
    static bool attr_done = false;
    if (!attr_done) {
        cudaFuncSetAttribute(traffic_smem_kernel,
                             cudaFuncAttributeMaxDynamicSharedMemorySize, SMEM_BYTES);
        cudaFuncSetAttribute(final_path_kernel,
                             cudaFuncAttributeMaxDynamicSharedMemorySize, SMEM_BYTES);
        attr_done = true;
    }

    const int LB4 = (N_LINKS / 4 + 255) / 256;    // float4 link kernels
    const int LB  = (N_LINKS + 255) / 256;
    const int PB  = (N_GROUPS + 127) / 128;

    traffic_pass1_kernel<<<PB, 128>>>(P, edges);            // bp == 0.5 exactly
    link_update_kernel<<<LB4, 256>>>(L);

    traffic_smem_kernel<<<PERS_CTAS, PERS_THREADS, SMEM_BYTES>>>(P, edges);
    link_update_kernel<<<LB4, 256>>>(L);

    traffic_smem_kernel<<<PERS_CTAS, PERS_THREADS, SMEM_BYTES>>>(P, edges);
    link_update_final_kernel<<<LB, 256>>>(L, out);

    final_path_kernel<<<PERS_CTAS, PERS_THREADS, SMEM_BYTES>>>(edges, out);
}

// round 6
// speedup vs baseline: 1.0369x; 1.0369x over previous
#include <cuda_runtime.h>

#define N_PATHS 1000000
#define N_LINKS 50000
#define K_HOPS  8
#define N_REP   8

// Scratch: __device__ globals. Zero-init at module load; link_update re-zeroes
// g_T each pass, so "g_T == 0 on entry" is an invariant across graph replays.
// g_bp is written by the first link_update before its first read (pass 1 is
// specialized to bp == 0.5).
__device__ float g_T[N_REP][N_LINKS];
__device__ float g_bp[N_LINKS];
__device__ float g_Xl[N_LINKS];

// A = P[:,1] for 4 consecutive paths via 3 float4 loads (3*p0 % 4 == 0).
__device__ __forceinline__ void load_A4(const float* __restrict__ P, int p0,
                                        float& t0, float& t1, float& t2, float& t3) {
    const float4* P4 = reinterpret_cast<const float4*>(P + 3 * p0);
    float4 a = __ldg(&P4[0]);
    float4 b = __ldg(&P4[1]);
    float4 c = __ldg(&P4[2]);
    t0 = a.y; t1 = b.x; t2 = b.w; t3 = c.z;
}

// Pass 1: bp == 0.5 -> t_k = A[p] * 0.5^k. No gathers, no dependency chain:
// pure scatter throughput, so run 8 paths per thread for double ILP.
__global__ void __launch_bounds__(128) traffic_pass1_kernel(const float* __restrict__ P,
                                                            const int*   __restrict__ edges) {
    int g = blockIdx.x * blockDim.x + threadIdx.x;   // group of 8 paths
    if (g >= N_PATHS / 8) return;
    int p0 = g * 8;
    float* __restrict__ T = g_T[threadIdx.x & (N_REP - 1)];

    float t0, t1, t2, t3, t4, t5, t6, t7;
    load_A4(P, p0,     t0, t1, t2, t3);
    load_A4(P, p0 + 4, t4, t5, t6, t7);

#pragma unroll
    for (int k = 0; k < K_HOPS; k++) {
        const int* ek = edges + (size_t)k * N_PATHS + p0;
        int4 a4 = *reinterpret_cast<const int4*>(ek);
        int4 b4 = *reinterpret_cast<const int4*>(ek + 4);
        atomicAdd(&T[a4.x - N_PATHS], t0);
        atomicAdd(&T[a4.y - N_PATHS], t1);
        atomicAdd(&T[a4.z - N_PATHS], t2);
        atomicAdd(&T[a4.w - N_PATHS], t3);
        atomicAdd(&T[b4.x - N_PATHS], t4);
        atomicAdd(&T[b4.y - N_PATHS], t5);
        atomicAdd(&T[b4.z - N_PATHS], t6);
        atomicAdd(&T[b4.w - N_PATHS], t7);
        t0 *= 0.5f; t1 *= 0.5f; t2 *= 0.5f; t3 *= 0.5f;
        t4 *= 0.5f; t5 *= 0.5f; t6 *= 0.5f; t7 *= 0.5f;
    }
}

// Passes 2/3 (unchanged from the 158us best): T[e] += t (RED into one of 8
// replicas), then t *= (1 - bp[e]); bp (200KB) stays L1-resident.
__global__ void __launch_bounds__(128) traffic_kernel(const float* __restrict__ P,
                                                      const int*   __restrict__ edges) {
    int p0 = (blockIdx.x * blockDim.x + threadIdx.x) * 4;
    if (p0 >= N_PATHS) return;
    float* __restrict__ T = g_T[threadIdx.x & (N_REP - 1)];

    float t0, t1, t2, t3;
    load_A4(P, p0, t0, t1, t2, t3);

#pragma unroll
    for (int k = 0; k < K_HOPS; k++) {
        int4 e4 = *reinterpret_cast<const int4*>(edges + (size_t)k * N_PATHS + p0);
        int e0 = e4.x - N_PATHS;
        int e1 = e4.y - N_PATHS;
        int e2 = e4.z - N_PATHS;
        int e3 = e4.w - N_PATHS;

        atomicAdd(&T[e0], t0);
        atomicAdd(&T[e1], t1);
        atomicAdd(&T[e2], t2);
        atomicAdd(&T[e3], t3);

        t0 *= 1.0f - __ldg(&g_bp[e0]);
        t1 *= 1.0f - __ldg(&g_bp[e1]);
        t2 *= 1.0f - __ldg(&g_bp[e2]);
        t3 *= 1.0f - __ldg(&g_bp[e3]);
    }
}

// Mid-iteration link update: one thread per LINK (196 CTAs -> real occupancy,
// 8-way MLP on the replica loads). rho = sum_r T_r / cap; bp update; re-zero T.
__global__ void __launch_bounds__(256) link_update_kernel(const float* __restrict__ L) {
    int l = blockIdx.x * blockDim.x + threadIdx.x;
    if (l >= N_LINKS) return;

    float v0 = g_T[0][l], v1 = g_T[1][l], v2 = g_T[2][l], v3 = g_T[3][l];
    float v4 = g_T[4][l], v5 = g_T[5][l], v6 = g_T[6][l], v7 = g_T[7][l];
    g_T[0][l] = 0.f; g_T[1][l] = 0.f; g_T[2][l] = 0.f; g_T[3][l] = 0.f;
    g_T[4][l] = 0.f; g_T[5][l] = 0.f; g_T[6][l] = 0.f; g_T[7][l] = 0.f;
    float Tl = ((v0 + v1) + (v2 + v3)) + ((v4 + v5) + (v6 + v7));

    float rho = Tl / (__ldg(&L[l]) / 1000.0f);
    float r2 = rho * rho, r4 = r2 * r2, r8 = r4 * r4, r16 = r8 * r8, r32 = r16 * r16;
    g_bp[l] = (1.0f - rho) * r32 / (1.0f - r32 * rho + 1e-8f);
}

// Final link update (iteration 3) fused with per-link epilogue.
__global__ void __launch_bounds__(256) link_update_final_kernel(const float* __restrict__ L,
                                                                float* __restrict__ out) {
    int l = blockIdx.x * blockDim.x + threadIdx.x;
    if (l >= N_LINKS) return;

    float v0 = g_T[0][l], v1 = g_T[1][l], v2 = g_T[2][l], v3 = g_T[3][l];
    float v4 = g_T[4][l], v5 = g_T[5][l], v6 = g_T[6][l], v7 = g_T[7][l];
    g_T[0][l] = 0.f; g_T[1][l] = 0.f; g_T[2][l] = 0.f; g_T[3][l] = 0.f;
    g_T[4][l] = 0.f; g_T[5][l] = 0.f; g_T[6][l] = 0.f; g_T[7][l] = 0.f;
    float Tl = ((v0 + v1) + (v2 + v3)) + ((v4 + v5) + (v6 + v7));

    float Lraw = __ldg(&L[l]);
    float rho  = Tl / (Lraw / 1000.0f);

    float r2 = rho * rho, r4 = r2 * r2, r8 = r4 * r4, r16 = r8 * r8, r32 = r16 * r16;
    float r33 = r32 * rho;
    float pi0 = (1.0f - rho) / (1.0f - r33);

    float s = 1.0f, pw = 1.0f;
#pragma unroll
    for (int m = 1; m <= 32; m++) { pw *= rho; s += (float)m * pw; }

    float Lq   = pi0 * s / 32.0f;
    float pi0f = pi0 * r32;
    float Xl   = Lq * 32000.0f / Lraw;

    g_Xl[l] = Xl;

    out[N_PATHS + 3 * l + 0] = Lq;
    out[N_PATHS + 3 * l + 1] = rho;
    out[N_PATHS + 3 * l + 2] = pi0f;
}

// res[p] = sum_k X_l[e[k,p]] (identity segment ids -> gather-sum); X_l L1-resident.
__global__ void __launch_bounds__(128) final_path_kernel(const int* __restrict__ edges,
                                                         float* __restrict__ out) {
    int p0 = (blockIdx.x * blockDim.x + threadIdx.x) * 4;
    if (p0 >= N_PATHS) return;

    float s0 = 0.f, s1 = 0.f, s2 = 0.f, s3 = 0.f;
#pragma unroll
    for (int k = 0; k < K_HOPS; k++) {
        int4 e4 = *reinterpret_cast<const int4*>(edges + (size_t)k * N_PATHS + p0);
        s0 += __ldg(&g_Xl[e4.x - N_PATHS]);
        s1 += __ldg(&g_Xl[e4.y - N_PATHS]);
        s2 += __ldg(&g_Xl[e4.z - N_PATHS]);
        s3 += __ldg(&g_Xl[e4.w - N_PATHS]);
    }
    *reinterpret_cast<float4*>(out + p0) = make_float4(s0, s1, s2, s3);
}

extern "C" void kernel_launch(void* const* d_in, const int* in_sizes, int n_in,
                              void* d_out, int out_size) {
    const float* P     = (const float*)d_in[0];   // (N_PATHS, 3)
    const float* L     = (const float*)d_in[1];   // (N_LINKS, 1)
    // d_in[2] = pl_paths: identity, unused
    const int*   edges = (const int*)d_in[3];     // (K_HOPS, N_PATHS)
    float* out = (float*)d_out;

    const int LB  = (N_LINKS + 255) / 256;        // 196 CTAs
    const int PB4 = (N_PATHS / 4 + 127) / 128;    // 1954 CTAs (4 paths/thread)
    const int PB8 = (N_PATHS / 8 + 127) / 128;    //  977 CTAs (8 paths/thread)

    traffic_pass1_kernel<<<PB8, 128>>>(P, edges);   // bp == 0.5 exactly
    link_update_kernel<<<LB, 256>>>(L);

    traffic_kernel<<<PB4, 128>>>(P, edges);
    link_update_kernel<<<LB, 256>>>(L);

    traffic_kernel<<<PB4, 128>>>(P, edges);
    link_update_final_kernel<<<LB, 256>>>(L, out);

    final_path_kernel<<<PB4, 128>>>(edges, out);
}